// round 7
// baseline (speedup 1.0000x reference)
#include <cuda_runtime.h>
#include <cuda_bf16.h>
#include <cstdint>

#define S_TOT  4096
#define A_TOT  1024
#define D_IN   5
#define H      64
#define M_TILE 128
#define NTHR   128

// ---------------- helpers ----------------
__device__ __forceinline__ uint32_t smem_u32(const void* p) {
    uint32_t a;
    asm("{ .reg .u64 t; cvta.to.shared.u64 t, %1; cvt.u32.u64 %0, t; }" : "=r"(a) : "l"(p));
    return a;
}
__device__ __forceinline__ float ex2f(float x) {
    float y; asm("ex2.approx.ftz.f32 %0, %1;" : "=f"(y) : "f"(x)); return y;
}
// Two accurate tanh sharing one reciprocal: 2x EX2 + 1x RCP (1.5 MUFU/tanh).
__device__ __forceinline__ float2 tanh2(float a, float b) {
    const float c = 2.885390081777927f;                 // 2*log2(e)
    a = fminf(9.0f, fmaxf(-9.0f, a));
    b = fminf(9.0f, fmaxf(-9.0f, b));
    float za = ex2f(a * c), zb = ex2f(b * c);
    float pa = za + 1.0f, pb = zb + 1.0f;
    float r2 = __fdividef(2.0f, pa * pb);
    return make_float2(1.0f - r2 * pb, 1.0f - r2 * pa);
}
__device__ __forceinline__ void split_pack(float x, float y, uint32_t& hi, uint32_t& lo) {
    __nv_bfloat162 h2 = __floats2bfloat162_rn(x, y);
    float hx = __bfloat162float(__low2bfloat16(h2));
    float hy = __bfloat162float(__high2bfloat16(h2));
    __nv_bfloat162 l2 = __floats2bfloat162_rn(x - hx, y - hy);
    hi = *reinterpret_cast<uint32_t*>(&h2);
    lo = *reinterpret_cast<uint32_t*>(&l2);
}
__device__ __forceinline__ void ldsm_x4(uint32_t* r, uint32_t addr) {
    asm volatile("ldmatrix.sync.aligned.m8n8.x4.shared.b16 {%0,%1,%2,%3}, [%4];"
                 : "=r"(r[0]), "=r"(r[1]), "=r"(r[2]), "=r"(r[3]) : "r"(addr));
}
__device__ __forceinline__ void ldsm_x2t(uint32_t* r, uint32_t addr) {
    asm volatile("ldmatrix.sync.aligned.m8n8.x2.trans.shared.b16 {%0,%1}, [%2];"
                 : "=r"(r[0]), "=r"(r[1]) : "r"(addr));
}
__device__ __forceinline__ void mma_bf16(float* c, const uint32_t* a, const uint32_t* b) {
    asm volatile("mma.sync.aligned.m16n8k16.row.col.f32.bf16.bf16.f32 "
                 "{%0,%1,%2,%3}, {%4,%5,%6,%7}, {%8,%9}, {%0,%1,%2,%3};"
                 : "+f"(c[0]), "+f"(c[1]), "+f"(c[2]), "+f"(c[3])
                 : "r"(a[0]), "r"(a[1]), "r"(a[2]), "r"(a[3]), "r"(b[0]), "r"(b[1]));
}

// Static smem (exactly 48 KB): MMA tiles. 16B chunks XOR-swizzled: chunk' = chunk ^ (row & 7).
struct SmemT {
    __align__(128) __nv_bfloat16 Ahi[M_TILE * H];   // 16 KB
    __align__(128) __nv_bfloat16 Alo[M_TILE * H];   // 16 KB
    __align__(128) __nv_bfloat16 Bhi[H * H];        // 8 KB
    __align__(128) __nv_bfloat16 Blo[H * H];        // 8 KB
};
// Dynamic smem: per-atom small weights (513 floats):
// W1[320] | b1[64] | b2[64] | w3[64] | b3[1]

__global__ __launch_bounds__(NTHR) void mlp_kernel(
    const float* __restrict__ g,  const float* __restrict__ W1, const float* __restrict__ b1,
    const float* __restrict__ W2, const float* __restrict__ b2,
    const float* __restrict__ W3, const float* __restrict__ b3, float* __restrict__ out)
{
    __shared__ SmemT sm;
    extern __shared__ float dynw[];
    float* sW1 = dynw;            // [5][64]
    float* sB1 = dynw + 320;
    float* sB2 = dynw + 384;
    float* sW3 = dynw + 448;
    float* sB3 = dynw + 512;

    const int tid  = threadIdx.x;
    const int wid  = tid >> 5;
    const int lane = tid & 31;
    const int a    = blockIdx.x;           // atom on x: adjacent CTAs -> adjacent out columns
    const int s0   = blockIdx.y * M_TILE;

    // ---- stage small per-atom weights into dynamic smem (coalesced) ----
    {
        const float* w1src = W1 + (size_t)a * D_IN * H;
        #pragma unroll
        for (int i = tid; i < D_IN * H; i += NTHR) sW1[i] = w1src[i];
        if (tid < H) {
            sB1[tid] = b1[(size_t)a * H + tid];
            sB2[tid] = b2[(size_t)a * H + tid];
            sW3[tid] = W3[(size_t)a * H + tid];
        }
        if (tid == 0) sB3[0] = b3[a];
    }

    // ---- stage B = W2[a], [k][n] layout, bf16 hi/lo, swizzled, vectorized ----
    {
        const float* W2a = W2 + (size_t)a * H * H;
        #pragma unroll
        for (int it = 0; it < 4; it++) {                 // 512 chunks / 128 thr
            int ch = tid + it * NTHR;                    // chunk id
            int k = ch >> 3, nc = ch & 7;                // k row, 8-col chunk
            const float4* src = (const float4*)(W2a + k * H + nc * 8);
            float4 w0 = src[0], w1 = src[1];
            uint32_t hi[4], lo[4];
            split_pack(w0.x, w0.y, hi[0], lo[0]);
            split_pack(w0.z, w0.w, hi[1], lo[1]);
            split_pack(w1.x, w1.y, hi[2], lo[2]);
            split_pack(w1.z, w1.w, hi[3], lo[3]);
            uint32_t off = (uint32_t)k * 128 + ((uint32_t)(nc ^ (k & 7)) << 4);
            *(uint4*)((char*)sm.Bhi + off) = make_uint4(hi[0], hi[1], hi[2], hi[3]);
            *(uint4*)((char*)sm.Blo + off) = make_uint4(lo[0], lo[1], lo[2], lo[3]);
        }
    }

    // this thread's descriptor vector (no barrier needed)
    float gd[D_IN];
    {
        const float* gp = g + ((size_t)(s0 + tid) * A_TOT + a) * D_IN;
        #pragma unroll
        for (int d = 0; d < D_IN; d++) gd[d] = __ldg(gp + d);
    }
    __syncthreads();   // dynw + B tiles ready

    // ---- layer 1: h1 = tanh(g . W1 + b1), split bf16 hi/lo into smem A ----
    {
        const int row = tid;
        #pragma unroll
        for (int c = 0; c < 8; c++) {                    // 8 cols per 16B chunk
            int j0 = c * 8;
            float4 acc0 = *(const float4*)&sB1[j0];
            float4 acc1 = *(const float4*)&sB1[j0 + 4];
            #pragma unroll
            for (int d = 0; d < D_IN; d++) {
                float4 w0 = *(const float4*)&sW1[d * H + j0];
                float4 w1 = *(const float4*)&sW1[d * H + j0 + 4];
                acc0.x = fmaf(gd[d], w0.x, acc0.x);
                acc0.y = fmaf(gd[d], w0.y, acc0.y);
                acc0.z = fmaf(gd[d], w0.z, acc0.z);
                acc0.w = fmaf(gd[d], w0.w, acc0.w);
                acc1.x = fmaf(gd[d], w1.x, acc1.x);
                acc1.y = fmaf(gd[d], w1.y, acc1.y);
                acc1.z = fmaf(gd[d], w1.z, acc1.z);
                acc1.w = fmaf(gd[d], w1.w, acc1.w);
            }
            uint32_t phi[4], plo[4];
            float2 t0 = tanh2(acc0.x, acc0.y);
            float2 t1 = tanh2(acc0.z, acc0.w);
            float2 t2 = tanh2(acc1.x, acc1.y);
            float2 t3 = tanh2(acc1.z, acc1.w);
            split_pack(t0.x, t0.y, phi[0], plo[0]);
            split_pack(t1.x, t1.y, phi[1], plo[1]);
            split_pack(t2.x, t2.y, phi[2], plo[2]);
            split_pack(t3.x, t3.y, phi[3], plo[3]);
            uint32_t byte = (uint32_t)row * 128 + (((uint32_t)(c ^ (row & 7))) << 4);
            *(uint4*)((char*)sm.Ahi + byte) = make_uint4(phi[0], phi[1], phi[2], phi[3]);
            *(uint4*)((char*)sm.Alo + byte) = make_uint4(plo[0], plo[1], plo[2], plo[3]);
        }
    }
    __syncthreads();

    // ---- layer 2 on tensor cores: C = Ahi*Bhi + Ahi*Blo + Alo*Bhi ----
    float C[2][8][4];
    #pragma unroll
    for (int rt = 0; rt < 2; rt++)
        #pragma unroll
        for (int nt = 0; nt < 8; nt++)
            #pragma unroll
            for (int i = 0; i < 4; i++) C[rt][nt][i] = 0.0f;

    #pragma unroll
    for (int ks = 0; ks < 4; ks++) {
        uint32_t ahi[2][4], alo[2][4];
        #pragma unroll
        for (int rt = 0; rt < 2; rt++) {
            int arow = wid * 32 + rt * 16 + (lane & 15);
            uint32_t chunk = (uint32_t)((ks * 2 + (lane >> 4)) ^ (arow & 7));
            uint32_t ab = (uint32_t)arow * 128 + (chunk << 4);
            ldsm_x4(ahi[rt], smem_u32((char*)sm.Ahi + ab));
            ldsm_x4(alo[rt], smem_u32((char*)sm.Alo + ab));
        }
        #pragma unroll
        for (int nt = 0; nt < 8; nt++) {
            int brow = ks * 16 + (lane & 15);
            uint32_t bb = (uint32_t)brow * 128 + ((uint32_t)(nt ^ (brow & 7)) << 4);
            uint32_t bhi[2], blo[2];
            ldsm_x2t(bhi, smem_u32((char*)sm.Bhi + bb));
            ldsm_x2t(blo, smem_u32((char*)sm.Blo + bb));
            #pragma unroll
            for (int rt = 0; rt < 2; rt++) {
                mma_bf16(C[rt][nt], ahi[rt], bhi);
                mma_bf16(C[rt][nt], ahi[rt], blo);
                mma_bf16(C[rt][nt], alo[rt], bhi);
            }
        }
    }

    // ---- epilogue: +b2, tanh, dot W3, row-reduce, direct [S,A] store ----
    {
        float e[4] = {0.f, 0.f, 0.f, 0.f};              // rows q, q+8, q+16, q+24
        const int c2 = (lane & 3) * 2;
        #pragma unroll
        for (int nt = 0; nt < 8; nt++) {
            int col = nt * 8 + c2;
            float2 bb = *(const float2*)&sB2[col];
            float2 ww = *(const float2*)&sW3[col];
            #pragma unroll
            for (int rt = 0; rt < 2; rt++) {
                float2 t0 = tanh2(C[rt][nt][0] + bb.x, C[rt][nt][1] + bb.y);
                float2 t1 = tanh2(C[rt][nt][2] + bb.x, C[rt][nt][3] + bb.y);
                e[rt * 2 + 0] = fmaf(t0.x, ww.x, fmaf(t0.y, ww.y, e[rt * 2 + 0]));
                e[rt * 2 + 1] = fmaf(t1.x, ww.x, fmaf(t1.y, ww.y, e[rt * 2 + 1]));
            }
        }
        #pragma unroll
        for (int i = 0; i < 4; i++) {
            e[i] += __shfl_xor_sync(0xFFFFFFFFu, e[i], 1);
            e[i] += __shfl_xor_sync(0xFFFFFFFFu, e[i], 2);
        }
        if ((lane & 3) == 0) {
            float e3 = sB3[0];
            int q = lane >> 2;
            int r = s0 + wid * 32 + q;                   // global struct row
            out[(size_t)(r)      * A_TOT + a] = e[0] + e3;
            out[(size_t)(r + 8)  * A_TOT + a] = e[1] + e3;
            out[(size_t)(r + 16) * A_TOT + a] = e[2] + e3;
            out[(size_t)(r + 24) * A_TOT + a] = e[3] + e3;
        }
    }
}

extern "C" void kernel_launch(void* const* d_in, const int* in_sizes, int n_in,
                              void* d_out, int out_size)
{
    const float* g  = (const float*)d_in[0];
    const float* W1 = (const float*)d_in[1];
    const float* b1 = (const float*)d_in[2];
    const float* W2 = (const float*)d_in[3];
    const float* b2 = (const float*)d_in[4];
    const float* W3 = (const float*)d_in[5];
    const float* b3 = (const float*)d_in[6];
    float* out = (float*)d_out;

    static bool attr_set = false;
    const int dyn_bytes = 513 * sizeof(float);
    if (!attr_set) {
        cudaFuncSetAttribute(mlp_kernel, cudaFuncAttributeMaxDynamicSharedMemorySize, dyn_bytes);
        attr_set = true;
    }

    // atom on grid.x so adjacent CTAs write adjacent out columns (L2 store merging);
    // single kernel type -> ncu -s 5 -c 1 must land on mlp_kernel.
    mlp_kernel<<<dim3(A_TOT, S_TOT / M_TILE), NTHR, dyn_bytes>>>(g, W1, b1, W2, b2, W3, b3, out);
}

// round 8
// speedup vs baseline: 2.3090x; 2.3090x over previous
#include <cuda_runtime.h>
#include <cuda_fp16.h>
#include <cstdint>

#define S_TOT  4096
#define A_TOT  1024
#define D_IN   5
#define H      64
#define M_TILE 128
#define NTHR   128

// ---------------- helpers ----------------
__device__ __forceinline__ uint32_t smem_u32(const void* p) {
    uint32_t a;
    asm("{ .reg .u64 t; cvta.to.shared.u64 t, %1; cvt.u32.u64 %0, t; }" : "=r"(a) : "l"(p));
    return a;
}
__device__ __forceinline__ float ex2f(float x) {
    float y; asm("ex2.approx.ftz.f32 %0, %1;" : "=f"(y) : "f"(x)); return y;
}
__device__ __forceinline__ float rcpf(float x) {
    float y; asm("rcp.approx.ftz.f32 %0, %1;" : "=f"(y) : "f"(x)); return y;
}
__device__ __forceinline__ float tanh_approx(float x) {
    float y; asm("tanh.approx.f32 %0, %1;" : "=f"(y) : "f"(x)); return y;
}
// Two accurate tanh sharing one reciprocal; only upper clamp needed (z->0 is safe).
__device__ __forceinline__ float2 tanh2(float a, float b) {
    const float c = 2.885390081777927f;                 // 2*log2(e)
    a = fminf(a, 9.0f);
    b = fminf(b, 9.0f);
    float pa = ex2f(a * c) + 1.0f;
    float pb = ex2f(b * c) + 1.0f;
    float r2 = 2.0f * rcpf(pa * pb);
    return make_float2(1.0f - r2 * pb, 1.0f - r2 * pa);
}
__device__ __forceinline__ void split_pack_h(float x, float y, uint32_t& hi, uint32_t& lo) {
    __half2 h2 = __floats2half2_rn(x, y);
    float hx = __low2float(h2), hy = __high2float(h2);
    __half2 l2 = __floats2half2_rn(x - hx, y - hy);
    hi = *reinterpret_cast<uint32_t*>(&h2);
    lo = *reinterpret_cast<uint32_t*>(&l2);
}
__device__ __forceinline__ void ldsm_x4(uint32_t* r, uint32_t addr) {
    asm volatile("ldmatrix.sync.aligned.m8n8.x4.shared.b16 {%0,%1,%2,%3}, [%4];"
                 : "=r"(r[0]), "=r"(r[1]), "=r"(r[2]), "=r"(r[3]) : "r"(addr));
}
__device__ __forceinline__ void ldsm_x2t(uint32_t* r, uint32_t addr) {
    asm volatile("ldmatrix.sync.aligned.m8n8.x2.trans.shared.b16 {%0,%1}, [%2];"
                 : "=r"(r[0]), "=r"(r[1]) : "r"(addr));
}
__device__ __forceinline__ void mma_f16(float* c, const uint32_t* a, const uint32_t* b) {
    asm volatile("mma.sync.aligned.m16n8k16.row.col.f32.f16.f16.f32 "
                 "{%0,%1,%2,%3}, {%4,%5,%6,%7}, {%8,%9}, {%0,%1,%2,%3};"
                 : "+f"(c[0]), "+f"(c[1]), "+f"(c[2]), "+f"(c[3])
                 : "r"(a[0]), "r"(a[1]), "r"(a[2]), "r"(a[3]), "r"(b[0]), "r"(b[1]));
}

// Static smem (32 KB): fp16 MMA tiles. 16B chunks XOR-swizzled: chunk' = chunk ^ (row & 7).
struct SmemT {
    __align__(128) __half A  [M_TILE * H];   // 16 KB (h1, fp16 single)
    __align__(128) __half Bhi[H * H];        // 8 KB  (W2 fp16 hi)
    __align__(128) __half Blo[H * H];        // 8 KB  (W2 fp16 lo)
};
// Dynamic smem: W1[320] | b1[64] | b2[64] | w3[64] | b3[1]

__global__ __launch_bounds__(NTHR, 5) void mlp_kernel(
    const float* __restrict__ g,  const float* __restrict__ W1, const float* __restrict__ b1,
    const float* __restrict__ W2, const float* __restrict__ b2,
    const float* __restrict__ W3, const float* __restrict__ b3, float* __restrict__ out)
{
    __shared__ SmemT sm;
    extern __shared__ float dynw[];
    float* sW1 = dynw;            // [5][64]
    float* sB1 = dynw + 320;
    float* sB2 = dynw + 384;
    float* sW3 = dynw + 448;
    float* sB3 = dynw + 512;

    const int tid  = threadIdx.x;
    const int wid  = tid >> 5;
    const int lane = tid & 31;
    const int a    = blockIdx.y;          // R6 raster: consecutive CTAs share atom weights
    const int s0   = blockIdx.x * M_TILE;

    // ---- stage small per-atom weights into dynamic smem ----
    {
        const float* w1src = W1 + (size_t)a * D_IN * H;
        #pragma unroll
        for (int i = tid; i < D_IN * H; i += NTHR) sW1[i] = w1src[i];
        if (tid < H) {
            sB1[tid] = b1[(size_t)a * H + tid];
            sB2[tid] = b2[(size_t)a * H + tid];
            sW3[tid] = W3[(size_t)a * H + tid];
        }
        if (tid == 0) sB3[0] = b3[a];
    }

    // ---- stage B = W2[a], [k][n], fp16 hi/lo, swizzled, vectorized ----
    {
        const float* W2a = W2 + (size_t)a * H * H;
        #pragma unroll
        for (int it = 0; it < 4; it++) {                 // 512 8-float chunks / 128 thr
            int ch = tid + it * NTHR;
            int k = ch >> 3, nc = ch & 7;
            const float4* src = (const float4*)(W2a + k * H + nc * 8);
            float4 w0 = src[0], w1 = src[1];
            uint32_t hi[4], lo[4];
            split_pack_h(w0.x, w0.y, hi[0], lo[0]);
            split_pack_h(w0.z, w0.w, hi[1], lo[1]);
            split_pack_h(w1.x, w1.y, hi[2], lo[2]);
            split_pack_h(w1.z, w1.w, hi[3], lo[3]);
            uint32_t off = (uint32_t)k * 128 + ((uint32_t)(nc ^ (k & 7)) << 4);
            *(uint4*)((char*)sm.Bhi + off) = make_uint4(hi[0], hi[1], hi[2], hi[3]);
            *(uint4*)((char*)sm.Blo + off) = make_uint4(lo[0], lo[1], lo[2], lo[3]);
        }
    }

    // this thread's descriptor vector
    float gd[D_IN];
    {
        const float* gp = g + ((size_t)(s0 + tid) * A_TOT + a) * D_IN;
        #pragma unroll
        for (int d = 0; d < D_IN; d++) gd[d] = __ldg(gp + d);
    }
    __syncthreads();

    // ---- layer 1: h1 = tanh(g . W1 + b1) -> fp16 into smem A ----
    {
        const int row = tid;
        #pragma unroll
        for (int c = 0; c < 8; c++) {                    // 8 cols per 16B chunk
            int j0 = c * 8;
            float4 acc0 = *(const float4*)&sB1[j0];
            float4 acc1 = *(const float4*)&sB1[j0 + 4];
            #pragma unroll
            for (int d = 0; d < D_IN; d++) {
                float4 w0 = *(const float4*)&sW1[d * H + j0];
                float4 w1 = *(const float4*)&sW1[d * H + j0 + 4];
                acc0.x = fmaf(gd[d], w0.x, acc0.x);
                acc0.y = fmaf(gd[d], w0.y, acc0.y);
                acc0.z = fmaf(gd[d], w0.z, acc0.z);
                acc0.w = fmaf(gd[d], w0.w, acc0.w);
                acc1.x = fmaf(gd[d], w1.x, acc1.x);
                acc1.y = fmaf(gd[d], w1.y, acc1.y);
                acc1.z = fmaf(gd[d], w1.z, acc1.z);
                acc1.w = fmaf(gd[d], w1.w, acc1.w);
            }
            float2 t0 = tanh2(acc0.x, acc0.y);
            float2 t1 = tanh2(acc0.z, acc0.w);
            float2 t2 = tanh2(acc1.x, acc1.y);
            float2 t3 = tanh2(acc1.z, acc1.w);
            __half2 p0 = __floats2half2_rn(t0.x, t0.y);
            __half2 p1 = __floats2half2_rn(t1.x, t1.y);
            __half2 p2 = __floats2half2_rn(t2.x, t2.y);
            __half2 p3 = __floats2half2_rn(t3.x, t3.y);
            uint32_t byte = (uint32_t)row * 128 + (((uint32_t)(c ^ (row & 7))) << 4);
            *(uint4*)((char*)sm.A + byte) = make_uint4(
                *reinterpret_cast<uint32_t*>(&p0), *reinterpret_cast<uint32_t*>(&p1),
                *reinterpret_cast<uint32_t*>(&p2), *reinterpret_cast<uint32_t*>(&p3));
        }
    }
    __syncthreads();

    // ---- layer 2 (tensor cores, C = A*Bhi + A*Blo) + fused epilogue, 2 n-halves ----
    float e[4] = {0.f, 0.f, 0.f, 0.f};                  // rows q, q+8, q+16, q+24
    const int c2 = (lane & 3) * 2;
    #pragma unroll
    for (int nh = 0; nh < 2; nh++) {
        float C[2][4][4];
        #pragma unroll
        for (int rt = 0; rt < 2; rt++)
            #pragma unroll
            for (int nt = 0; nt < 4; nt++)
                #pragma unroll
                for (int i = 0; i < 4; i++) C[rt][nt][i] = 0.0f;

        #pragma unroll
        for (int ks = 0; ks < 4; ks++) {
            uint32_t af[2][4];
            #pragma unroll
            for (int rt = 0; rt < 2; rt++) {
                int arow = wid * 32 + rt * 16 + (lane & 15);
                uint32_t chunk = (uint32_t)((ks * 2 + (lane >> 4)) ^ (arow & 7));
                ldsm_x4(af[rt], smem_u32((char*)sm.A + (uint32_t)arow * 128 + (chunk << 4)));
            }
            #pragma unroll
            for (int nt = 0; nt < 4; nt++) {
                int ntc = nh * 4 + nt;
                int brow = ks * 16 + (lane & 15);
                uint32_t bb = (uint32_t)brow * 128 + ((uint32_t)(ntc ^ (brow & 7)) << 4);
                uint32_t bhi[2], blo[2];
                ldsm_x2t(bhi, smem_u32((char*)sm.Bhi + bb));
                ldsm_x2t(blo, smem_u32((char*)sm.Blo + bb));
                #pragma unroll
                for (int rt = 0; rt < 2; rt++) {
                    mma_f16(C[rt][nt], af[rt], bhi);
                    mma_f16(C[rt][nt], af[rt], blo);
                }
            }
        }

        // partial epilogue for columns [nh*32, nh*32+32)
        #pragma unroll
        for (int nt = 0; nt < 4; nt++) {
            int col = (nh * 4 + nt) * 8 + c2;
            float2 bb = *(const float2*)&sB2[col];
            float2 ww = *(const float2*)&sW3[col];
            #pragma unroll
            for (int rt = 0; rt < 2; rt++) {
                float t0 = tanh_approx(C[rt][nt][0] + bb.x);
                float t1 = tanh_approx(C[rt][nt][1] + bb.y);
                float t2 = tanh_approx(C[rt][nt][2] + bb.x);
                float t3 = tanh_approx(C[rt][nt][3] + bb.y);
                e[rt * 2 + 0] = fmaf(t0, ww.x, fmaf(t1, ww.y, e[rt * 2 + 0]));
                e[rt * 2 + 1] = fmaf(t2, ww.x, fmaf(t3, ww.y, e[rt * 2 + 1]));
            }
        }
    }

    // ---- reduce + direct [S,A] store ----
    #pragma unroll
    for (int i = 0; i < 4; i++) {
        e[i] += __shfl_xor_sync(0xFFFFFFFFu, e[i], 1);
        e[i] += __shfl_xor_sync(0xFFFFFFFFu, e[i], 2);
    }
    if ((lane & 3) == 0) {
        float e3 = sB3[0];
        int q = lane >> 2;
        int r = s0 + wid * 32 + q;
        out[(size_t)(r)      * A_TOT + a] = e[0] + e3;
        out[(size_t)(r + 8)  * A_TOT + a] = e[1] + e3;
        out[(size_t)(r + 16) * A_TOT + a] = e[2] + e3;
        out[(size_t)(r + 24) * A_TOT + a] = e[3] + e3;
    }
}

extern "C" void kernel_launch(void* const* d_in, const int* in_sizes, int n_in,
                              void* d_out, int out_size)
{
    const float* g  = (const float*)d_in[0];
    const float* W1 = (const float*)d_in[1];
    const float* b1 = (const float*)d_in[2];
    const float* W2 = (const float*)d_in[3];
    const float* b2 = (const float*)d_in[4];
    const float* W3 = (const float*)d_in[5];
    const float* b3 = (const float*)d_in[6];
    float* out = (float*)d_out;

    static bool attr_set = false;
    const int dyn_bytes = 513 * sizeof(float);
    if (!attr_set) {
        cudaFuncSetAttribute(mlp_kernel, cudaFuncAttributeMaxDynamicSharedMemorySize, dyn_bytes);
        attr_set = true;
    }

    // s-tile on x, atom on y (R6 raster: weight-sharing CTAs temporally adjacent).
    mlp_kernel<<<dim3(S_TOT / M_TILE, A_TOT), NTHR, dyn_bytes>>>(g, W1, b1, W2, b2, W3, b3, out);
}

// round 9
// speedup vs baseline: 3.0138x; 1.3053x over previous
#include <cuda_runtime.h>
#include <cuda_fp16.h>
#include <cstdint>

#define S_TOT  4096
#define A_TOT  1024
#define D_IN   5
#define H      64
#define M_TILE 128
#define NTHR   128

// ---------------- helpers ----------------
__device__ __forceinline__ uint32_t smem_u32(const void* p) {
    uint32_t a;
    asm("{ .reg .u64 t; cvta.to.shared.u64 t, %1; cvt.u32.u64 %0, t; }" : "=r"(a) : "l"(p));
    return a;
}
__device__ __forceinline__ float ex2f(float x) {
    float y; asm("ex2.approx.ftz.f32 %0, %1;" : "=f"(y) : "f"(x)); return y;
}
__device__ __forceinline__ float rcpf(float x) {
    float y; asm("rcp.approx.ftz.f32 %0, %1;" : "=f"(y) : "f"(x)); return y;
}
__device__ __forceinline__ float tanh_approx(float x) {
    float y; asm("tanh.approx.f32 %0, %1;" : "=f"(y) : "f"(x)); return y;
}
// Two accurate tanh sharing one reciprocal; only upper clamp needed.
__device__ __forceinline__ float2 tanh2(float a, float b) {
    const float c = 2.885390081777927f;                 // 2*log2(e)
    a = fminf(a, 9.0f);
    b = fminf(b, 9.0f);
    float pa = ex2f(a * c) + 1.0f;
    float pb = ex2f(b * c) + 1.0f;
    float r2 = 2.0f * rcpf(pa * pb);
    return make_float2(1.0f - r2 * pb, 1.0f - r2 * pa);
}
__device__ __forceinline__ void split_pack_h(float x, float y, uint32_t& hi, uint32_t& lo) {
    __half2 h2 = __floats2half2_rn(x, y);
    float hx = __low2float(h2), hy = __high2float(h2);
    __half2 l2 = __floats2half2_rn(x - hx, y - hy);
    hi = *reinterpret_cast<uint32_t*>(&h2);
    lo = *reinterpret_cast<uint32_t*>(&l2);
}
__device__ __forceinline__ void ldsm_x2(uint32_t* r, uint32_t addr) {
    asm volatile("ldmatrix.sync.aligned.m8n8.x2.shared.b16 {%0,%1}, [%2];"
                 : "=r"(r[0]), "=r"(r[1]) : "r"(addr));
}
__device__ __forceinline__ void ldsm_x2t(uint32_t* r, uint32_t addr) {
    asm volatile("ldmatrix.sync.aligned.m8n8.x2.trans.shared.b16 {%0,%1}, [%2];"
                 : "=r"(r[0]), "=r"(r[1]) : "r"(addr));
}
__device__ __forceinline__ void mma_f16_k16(float* c, const uint32_t* a, const uint32_t* b) {
    asm volatile("mma.sync.aligned.m16n8k16.row.col.f32.f16.f16.f32 "
                 "{%0,%1,%2,%3}, {%4,%5,%6,%7}, {%8,%9}, {%0,%1,%2,%3};"
                 : "+f"(c[0]), "+f"(c[1]), "+f"(c[2]), "+f"(c[3])
                 : "r"(a[0]), "r"(a[1]), "r"(a[2]), "r"(a[3]), "r"(b[0]), "r"(b[1]));
}
__device__ __forceinline__ void mma_f16_k8(float* c, const uint32_t* a, uint32_t b) {
    asm volatile("mma.sync.aligned.m16n8k8.row.col.f32.f16.f16.f32 "
                 "{%0,%1,%2,%3}, {%4,%5}, {%6}, {%0,%1,%2,%3};"
                 : "+f"(c[0]), "+f"(c[1]), "+f"(c[2]), "+f"(c[3])
                 : "r"(a[0]), "r"(a[1]), "r"(b));
}

// Static smem (~22 KB). B tiles: rows 128B, 16B chunks XOR-swizzled (chunk ^= row&7).
// G tiles: 16B rows (no swizzle needed). W1 tiles: 8 rows x 128B, swizzled.
struct SmemT {
    __align__(128) __half Bhi[H * H];        // 8 KB  W2 hi [k][n]
    __align__(128) __half Blo[H * H];        // 8 KB  W2 lo
    __align__(128) __half Ghi[M_TILE * 8];   // 2 KB  g hi [row][k<=8]
    __align__(128) __half Glo[M_TILE * 8];   // 2 KB
    __align__(128) __half W1hi[8 * H];       // 1 KB  W1 hi [k<=8][n]
    __align__(128) __half W1lo[8 * H];       // 1 KB
};
// Dynamic smem: b1[64] | b2[64] | w3[64] | b3[1]  (193 floats)

__global__ __launch_bounds__(NTHR, 4) void mlp_kernel(
    const float* __restrict__ g,  const float* __restrict__ W1, const float* __restrict__ b1,
    const float* __restrict__ W2, const float* __restrict__ b2,
    const float* __restrict__ W3, const float* __restrict__ b3, float* __restrict__ out)
{
    __shared__ SmemT sm;
    extern __shared__ float dynw[];
    float* sB1 = dynw;
    float* sB2 = dynw + 64;
    float* sW3 = dynw + 128;
    float* sB3 = dynw + 192;

    const int tid  = threadIdx.x;
    const int wid  = tid >> 5;
    const int lane = tid & 31;
    const int a    = blockIdx.y;
    const int s0   = blockIdx.x * M_TILE;

    // ---- biases / w3 ----
    if (tid < H) {
        sB1[tid] = b1[(size_t)a * H + tid];
        sB2[tid] = b2[(size_t)a * H + tid];
        sW3[tid] = W3[(size_t)a * H + tid];
    }
    if (tid == 0) sB3[0] = b3[a];

    // ---- stage W2 -> Bhi/Blo, [k][n], fp16 hi/lo, swizzled, vectorized ----
    {
        const float* W2a = W2 + (size_t)a * H * H;
        #pragma unroll
        for (int it = 0; it < 4; it++) {
            int ch = tid + it * NTHR;
            int k = ch >> 3, nc = ch & 7;
            const float4* src = (const float4*)(W2a + k * H + nc * 8);
            float4 w0 = src[0], w1 = src[1];
            uint32_t hi[4], lo[4];
            split_pack_h(w0.x, w0.y, hi[0], lo[0]);
            split_pack_h(w0.z, w0.w, hi[1], lo[1]);
            split_pack_h(w1.x, w1.y, hi[2], lo[2]);
            split_pack_h(w1.z, w1.w, hi[3], lo[3]);
            uint32_t off = (uint32_t)k * 128 + ((uint32_t)(nc ^ (k & 7)) << 4);
            *(uint4*)((char*)sm.Bhi + off) = make_uint4(hi[0], hi[1], hi[2], hi[3]);
            *(uint4*)((char*)sm.Blo + off) = make_uint4(lo[0], lo[1], lo[2], lo[3]);
        }
    }

    // ---- stage W1 -> W1hi/W1lo tiles ([k][n], k padded 5->8) ----
    {
        if (tid < 24) {                                  // zero pad rows k=5..7
            int k = 5 + tid / 8, c = tid & 7;
            *(uint4*)((char*)sm.W1hi + k * 128 + c * 16) = make_uint4(0, 0, 0, 0);
            *(uint4*)((char*)sm.W1lo + k * 128 + c * 16) = make_uint4(0, 0, 0, 0);
        }
        const float* W1a = W1 + (size_t)a * D_IN * H;
        #pragma unroll
        for (int p = 0; p < 3; p++) {
            int e = p * NTHR + tid;
            if (e < D_IN * H) {
                int d = e >> 6, n = e & 63;
                float v = W1a[e];
                __half hi = __float2half_rn(v);
                __half lo = __float2half_rn(v - __half2float(hi));
                uint32_t off = (uint32_t)d * 128 + ((uint32_t)((n >> 3) ^ d) << 4) + ((n & 7) << 1);
                *(__half*)((char*)sm.W1hi + off) = hi;
                *(__half*)((char*)sm.W1lo + off) = lo;
            }
        }
    }

    // ---- stage g -> Ghi/Glo ([row][k], k padded 5->8), coalesced-ish ----
    {
        sm.Ghi[tid * 8 + 5] = __half(0.f); sm.Ghi[tid * 8 + 6] = __half(0.f); sm.Ghi[tid * 8 + 7] = __half(0.f);
        sm.Glo[tid * 8 + 5] = __half(0.f); sm.Glo[tid * 8 + 6] = __half(0.f); sm.Glo[tid * 8 + 7] = __half(0.f);
        const float* gp = g + ((size_t)s0 * A_TOT + a) * D_IN;
        const size_t rstride = (size_t)A_TOT * D_IN;
        #pragma unroll
        for (int p = 0; p < 5; p++) {
            int e = p * NTHR + tid;                      // 640 = 5*128
            int row = e / 5, d = e - row * 5;
            float v = __ldg(gp + (size_t)row * rstride + d);
            __half hi = __float2half_rn(v);
            __half lo = __float2half_rn(v - __half2float(hi));
            sm.Ghi[row * 8 + d] = hi;
            sm.Glo[row * 8 + d] = lo;
        }
    }
    __syncthreads();                                     // the only barrier

    // ---- layer 1 on tensor cores: C1 = b1 + Ghi*W1hi + Ghi*W1lo + Glo*W1hi ----
    uint32_t gfh[2][2], gfl[2][2];                       // A-frags m16k8 per rt
    #pragma unroll
    for (int rt = 0; rt < 2; rt++) {
        int row = wid * 32 + rt * 16 + (lane & 15);
        ldsm_x2(gfh[rt], smem_u32((char*)sm.Ghi + row * 16));
        ldsm_x2(gfl[rt], smem_u32((char*)sm.Glo + row * 16));
    }
    uint32_t w1h[4][2], w1l[4][2];                       // B-frags k8n8, 2 nt per ldsm
    #pragma unroll
    for (int ntp = 0; ntp < 4; ntp++) {
        int r8  = lane & 7;
        int ntx = 2 * ntp + ((lane >> 3) & 1);
        uint32_t off = (uint32_t)r8 * 128 + ((uint32_t)(ntx ^ r8) << 4);
        ldsm_x2t(w1h[ntp], smem_u32((char*)sm.W1hi + off));
        ldsm_x2t(w1l[ntp], smem_u32((char*)sm.W1lo + off));
    }

    const int c2 = (lane & 3) * 2;
    uint32_t Af[2][4][4];                                // layer-2 A-frags (fp16 h1)
    #pragma unroll
    for (int rt = 0; rt < 2; rt++) {
        #pragma unroll
        for (int nt = 0; nt < 8; nt++) {
            float C1[4];
            float2 bb = *(const float2*)&sB1[nt * 8 + c2];
            C1[0] = bb.x; C1[1] = bb.y; C1[2] = bb.x; C1[3] = bb.y;
            uint32_t bh = w1h[nt >> 1][nt & 1];
            uint32_t bl = w1l[nt >> 1][nt & 1];
            mma_f16_k8(C1, gfh[rt], bh);
            mma_f16_k8(C1, gfh[rt], bl);
            mma_f16_k8(C1, gfl[rt], bh);
            float2 t = tanh2(C1[0], C1[1]);
            float2 u = tanh2(C1[2], C1[3]);
            __half2 th = __floats2half2_rn(t.x, t.y);
            __half2 uh = __floats2half2_rn(u.x, u.y);
            Af[rt][nt >> 1][(nt & 1) * 2 + 0] = *reinterpret_cast<uint32_t*>(&th);
            Af[rt][nt >> 1][(nt & 1) * 2 + 1] = *reinterpret_cast<uint32_t*>(&uh);
        }
    }

    // ---- layer 2 (C = b2 + h1*(W2hi+W2lo)) + fused epilogue, 2 n-halves ----
    float e[4] = {0.f, 0.f, 0.f, 0.f};                   // rows q, q+8, q+16, q+24
    #pragma unroll
    for (int nh = 0; nh < 2; nh++) {
        float C[2][4][4];
        #pragma unroll
        for (int nt = 0; nt < 4; nt++) {
            float2 bb = *(const float2*)&sB2[(nh * 4 + nt) * 8 + c2];
            #pragma unroll
            for (int rt = 0; rt < 2; rt++) {
                C[rt][nt][0] = bb.x; C[rt][nt][1] = bb.y;
                C[rt][nt][2] = bb.x; C[rt][nt][3] = bb.y;
            }
        }
        #pragma unroll
        for (int ks = 0; ks < 4; ks++) {
            #pragma unroll
            for (int nt = 0; nt < 4; nt++) {
                int ntc = nh * 4 + nt;
                int brow = ks * 16 + (lane & 15);
                uint32_t bb = (uint32_t)brow * 128 + ((uint32_t)(ntc ^ (brow & 7)) << 4);
                uint32_t bhi[2], blo[2];
                ldsm_x2t(bhi, smem_u32((char*)sm.Bhi + bb));
                ldsm_x2t(blo, smem_u32((char*)sm.Blo + bb));
                #pragma unroll
                for (int rt = 0; rt < 2; rt++) {
                    mma_f16_k16(C[rt][nt], Af[rt][ks], bhi);
                    mma_f16_k16(C[rt][nt], Af[rt][ks], blo);
                }
            }
        }
        #pragma unroll
        for (int nt = 0; nt < 4; nt++) {
            float2 ww = *(const float2*)&sW3[(nh * 4 + nt) * 8 + c2];
            #pragma unroll
            for (int rt = 0; rt < 2; rt++) {
                float t0 = tanh_approx(C[rt][nt][0]);
                float t1 = tanh_approx(C[rt][nt][1]);
                float t2 = tanh_approx(C[rt][nt][2]);
                float t3 = tanh_approx(C[rt][nt][3]);
                e[rt * 2 + 0] = fmaf(t0, ww.x, fmaf(t1, ww.y, e[rt * 2 + 0]));
                e[rt * 2 + 1] = fmaf(t2, ww.x, fmaf(t3, ww.y, e[rt * 2 + 1]));
            }
        }
    }

    // ---- reduce + direct [S,A] store ----
    #pragma unroll
    for (int i = 0; i < 4; i++) {
        e[i] += __shfl_xor_sync(0xFFFFFFFFu, e[i], 1);
        e[i] += __shfl_xor_sync(0xFFFFFFFFu, e[i], 2);
    }
    if ((lane & 3) == 0) {
        float e3 = sB3[0];
        int q = lane >> 2;
        int r = s0 + wid * 32 + q;
        out[(size_t)(r)      * A_TOT + a] = e[0] + e3;
        out[(size_t)(r + 8)  * A_TOT + a] = e[1] + e3;
        out[(size_t)(r + 16) * A_TOT + a] = e[2] + e3;
        out[(size_t)(r + 24) * A_TOT + a] = e[3] + e3;
    }
}

extern "C" void kernel_launch(void* const* d_in, const int* in_sizes, int n_in,
                              void* d_out, int out_size)
{
    const float* g  = (const float*)d_in[0];
    const float* W1 = (const float*)d_in[1];
    const float* b1 = (const float*)d_in[2];
    const float* W2 = (const float*)d_in[3];
    const float* b2 = (const float*)d_in[4];
    const float* W3 = (const float*)d_in[5];
    const float* b3 = (const float*)d_in[6];
    float* out = (float*)d_out;

    const int dyn_bytes = 193 * sizeof(float);
    mlp_kernel<<<dim3(S_TOT / M_TILE, A_TOT), NTHR, dyn_bytes>>>(g, W1, b1, W2, b2, W3, b3, out);
}

// round 10
// speedup vs baseline: 3.1735x; 1.0530x over previous
#include <cuda_runtime.h>
#include <cuda_fp16.h>
#include <cstdint>

#define S_TOT  4096
#define A_TOT  1024
#define D_IN   5
#define H      64
#define M_TILE 128
#define NTHR   128
#define TILES  8
#define SPT    (M_TILE * TILES)   // structs per CTA

// ---------------- helpers ----------------
__device__ __forceinline__ uint32_t smem_u32(const void* p) {
    uint32_t a;
    asm("{ .reg .u64 t; cvta.to.shared.u64 t, %1; cvt.u32.u64 %0, t; }" : "=r"(a) : "l"(p));
    return a;
}
__device__ __forceinline__ float ex2f(float x) {
    float y; asm("ex2.approx.ftz.f32 %0, %1;" : "=f"(y) : "f"(x)); return y;
}
__device__ __forceinline__ float rcpf(float x) {
    float y; asm("rcp.approx.ftz.f32 %0, %1;" : "=f"(y) : "f"(x)); return y;
}
__device__ __forceinline__ float tanh_approx(float x) {
    float y; asm("tanh.approx.f32 %0, %1;" : "=f"(y) : "f"(x)); return y;
}
// Two accurate tanh sharing one reciprocal; only upper clamp needed.
__device__ __forceinline__ float2 tanh2(float a, float b) {
    const float c = 2.885390081777927f;                 // 2*log2(e)
    a = fminf(a, 9.0f);
    b = fminf(b, 9.0f);
    float pa = ex2f(a * c) + 1.0f;
    float pb = ex2f(b * c) + 1.0f;
    float r2 = 2.0f * rcpf(pa * pb);
    return make_float2(1.0f - r2 * pb, 1.0f - r2 * pa);
}
__device__ __forceinline__ void split_pack_h(float x, float y, uint32_t& hi, uint32_t& lo) {
    __half2 h2 = __floats2half2_rn(x, y);
    float hx = __low2float(h2), hy = __high2float(h2);
    __half2 l2 = __floats2half2_rn(x - hx, y - hy);
    hi = *reinterpret_cast<uint32_t*>(&h2);
    lo = *reinterpret_cast<uint32_t*>(&l2);
}
__device__ __forceinline__ void ldsm_x4t(uint32_t* r, uint32_t addr) {
    asm volatile("ldmatrix.sync.aligned.m8n8.x4.trans.shared.b16 {%0,%1,%2,%3}, [%4];"
                 : "=r"(r[0]), "=r"(r[1]), "=r"(r[2]), "=r"(r[3]) : "r"(addr));
}
__device__ __forceinline__ void mma_f16_k16(float* c, const uint32_t* a, const uint32_t* b) {
    asm volatile("mma.sync.aligned.m16n8k16.row.col.f32.f16.f16.f32 "
                 "{%0,%1,%2,%3}, {%4,%5,%6,%7}, {%8,%9}, {%0,%1,%2,%3};"
                 : "+f"(c[0]), "+f"(c[1]), "+f"(c[2]), "+f"(c[3])
                 : "r"(a[0]), "r"(a[1]), "r"(a[2]), "r"(a[3]), "r"(b[0]), "r"(b[1]));
}
__device__ __forceinline__ void mma_f16_k8(float* c, const uint32_t* a, uint32_t b) {
    asm volatile("mma.sync.aligned.m16n8k8.row.col.f32.f16.f16.f32 "
                 "{%0,%1,%2,%3}, {%4,%5}, {%6}, {%0,%1,%2,%3};"
                 : "+f"(c[0]), "+f"(c[1]), "+f"(c[2]), "+f"(c[3])
                 : "r"(a[0]), "r"(a[1]), "r"(b));
}

// Static smem (~27.5 KB). B tiles: rows 128B, 16B chunks XOR-swizzled (chunk ^= row&7).
struct SmemT {
    __align__(128) __half Bhi[H * H];          // 8 KB  W2 hi [k][n]
    __align__(128) __half Blo[H * H];          // 8 KB  W2 lo
    __align__(16)  float  G[2][M_TILE][8];     // 8 KB  g fp32, k padded 5->8, dbl-buffer
    __align__(16)  float  W1s[H][8];           // 2 KB  W1 fp32 [n][k], k padded
    float b1s[H], b2s[H], w3s[H], b3s;
};

__global__ __launch_bounds__(NTHR, 4) void mlp_kernel(
    const float* __restrict__ g,  const float* __restrict__ W1, const float* __restrict__ b1,
    const float* __restrict__ W2, const float* __restrict__ b2,
    const float* __restrict__ W3, const float* __restrict__ b3, float* __restrict__ out)
{
    __shared__ SmemT sm;
    const int tid  = threadIdx.x;
    const int wid  = tid >> 5;
    const int lane = tid & 31;
    const int a    = blockIdx.y;
    const int sBase = blockIdx.x * SPT;
    const size_t rstride = (size_t)A_TOT * D_IN;

    // ---- once-per-CTA staging ----
    if (tid < H) {
        sm.b1s[tid] = b1[(size_t)a * H + tid];
        sm.b2s[tid] = b2[(size_t)a * H + tid];
        sm.w3s[tid] = W3[(size_t)a * H + tid];
    }
    if (tid == 0) sm.b3s = b3[a];

    {   // W2 -> Bhi/Blo, fp16 hi/lo, swizzled
        const float* W2a = W2 + (size_t)a * H * H;
        #pragma unroll
        for (int it = 0; it < 4; it++) {
            int ch = tid + it * NTHR;
            int k = ch >> 3, nc = ch & 7;
            const float4* src = (const float4*)(W2a + k * H + nc * 8);
            float4 w0 = src[0], w1 = src[1];
            uint32_t hi[4], lo[4];
            split_pack_h(w0.x, w0.y, hi[0], lo[0]);
            split_pack_h(w0.z, w0.w, hi[1], lo[1]);
            split_pack_h(w1.x, w1.y, hi[2], lo[2]);
            split_pack_h(w1.z, w1.w, hi[3], lo[3]);
            uint32_t off = (uint32_t)k * 128 + ((uint32_t)(nc ^ (k & 7)) << 4);
            *(uint4*)((char*)sm.Bhi + off) = make_uint4(hi[0], hi[1], hi[2], hi[3]);
            *(uint4*)((char*)sm.Blo + off) = make_uint4(lo[0], lo[1], lo[2], lo[3]);
        }
    }
    {   // W1 fp32 transposed [n][k], k padded with zeros
        const float* W1a = W1 + (size_t)a * D_IN * H;
        #pragma unroll
        for (int it = 0; it < 4; it++) {
            int e = it * NTHR + tid;                     // e = n*8 + k
            int n = e >> 3, k = e & 7;
            sm.W1s[n][k] = (k < D_IN) ? W1a[k * H + n] : 0.0f;
        }
    }
    {   // G pads + first tile
        sm.G[0][tid][5] = 0.f; sm.G[0][tid][6] = 0.f; sm.G[0][tid][7] = 0.f;
        sm.G[1][tid][5] = 0.f; sm.G[1][tid][6] = 0.f; sm.G[1][tid][7] = 0.f;
        const float* gp = g + ((size_t)sBase * A_TOT + a) * D_IN;
        #pragma unroll
        for (int p = 0; p < 5; p++) {
            int e = p * NTHR + tid;
            int row = e / 5, d = e - row * 5;
            sm.G[0][row][d] = __ldg(gp + (size_t)row * rstride + d);
        }
    }
    __syncthreads();

    // ---- W1 fragments (built once, held in regs) ----
    uint32_t w1h[8], w1l[8];
    {
        int q = lane >> 2, k0 = (lane & 3) * 2;
        #pragma unroll
        for (int nt = 0; nt < 8; nt++) {
            float2 v = *(const float2*)&sm.W1s[nt * 8 + q][k0];
            split_pack_h(v.x, v.y, w1h[nt], w1l[nt]);
        }
    }

    const int c2i = (lane & 3) * 2;

    for (int t = 0; t < TILES; t++) {
        const int buf = t & 1;

        // ---- G fragments: direct build from fp32 smem (conflict-free LDS.64) ----
        uint32_t gfh[2][2], gfl[2][2];
        {
            int rbase = wid * 32 + (lane >> 2);
            #pragma unroll
            for (int rt = 0; rt < 2; rt++)
                #pragma unroll
                for (int hh = 0; hh < 2; hh++) {
                    int row = rbase + rt * 16 + hh * 8;
                    float2 v = *(const float2*)&sm.G[buf][row][c2i];
                    split_pack_h(v.x, v.y, gfh[rt][hh], gfl[rt][hh]);
                }
        }

        // ---- layer 1: C1 = b1 + Ghi*W1hi (k8) + [Ghi|Glo]*[W1lo|W1hi] (k16) ----
        uint32_t Af[2][4][4];
        #pragma unroll
        for (int rt = 0; rt < 2; rt++) {
            uint32_t ak16[4] = {gfh[rt][0], gfh[rt][1], gfl[rt][0], gfl[rt][1]};
            #pragma unroll
            for (int nt = 0; nt < 8; nt++) {
                float2 bb = *(const float2*)&sm.b1s[nt * 8 + c2i];
                float C1[4] = {bb.x, bb.y, bb.x, bb.y};
                mma_f16_k8(C1, gfh[rt], w1h[nt]);
                uint32_t bk16[2] = {w1l[nt], w1h[nt]};
                mma_f16_k16(C1, ak16, bk16);
                float2 tt = tanh2(C1[0], C1[1]);
                float2 uu = tanh2(C1[2], C1[3]);
                __half2 th = __floats2half2_rn(tt.x, tt.y);
                __half2 uh = __floats2half2_rn(uu.x, uu.y);
                Af[rt][nt >> 1][(nt & 1) * 2 + 0] = *reinterpret_cast<uint32_t*>(&th);
                Af[rt][nt >> 1][(nt & 1) * 2 + 1] = *reinterpret_cast<uint32_t*>(&uh);
            }
        }

        // ---- prefetch next g tile (overlaps layer 2) ----
        float gn[5];
        if (t + 1 < TILES) {
            const float* gp = g + ((size_t)(sBase + (t + 1) * M_TILE) * A_TOT + a) * D_IN;
            #pragma unroll
            for (int p = 0; p < 5; p++) {
                int e = p * NTHR + tid;
                int row = e / 5, d = e - row * 5;
                gn[p] = __ldg(gp + (size_t)row * rstride + d);
            }
        }

        // ---- layer 2 + fused epilogue ----
        float ee[4] = {0.f, 0.f, 0.f, 0.f};
        // x4t lane addressing (lane-consts)
        const int r_in  = lane & 7;
        const int sel_k = (lane >> 3) & 1;
        const int sel_n = lane >> 4;
        #pragma unroll
        for (int nh = 0; nh < 2; nh++) {
            float C[2][4][4];
            #pragma unroll
            for (int nt = 0; nt < 4; nt++) {
                float2 bb = *(const float2*)&sm.b2s[(nh * 4 + nt) * 8 + c2i];
                #pragma unroll
                for (int rt = 0; rt < 2; rt++) {
                    C[rt][nt][0] = bb.x; C[rt][nt][1] = bb.y;
                    C[rt][nt][2] = bb.x; C[rt][nt][3] = bb.y;
                }
            }
            #pragma unroll
            for (int ks = 0; ks < 4; ks++) {
                uint32_t bh[2][4], bl[2][4];
                #pragma unroll
                for (int ntp = 0; ntp < 2; ntp++) {
                    int row = ks * 16 + sel_k * 8 + r_in;
                    int ntc = nh * 4 + ntp * 2 + sel_n;
                    uint32_t off = (uint32_t)row * 128 + ((uint32_t)(ntc ^ r_in) << 4);
                    ldsm_x4t(bh[ntp], smem_u32((char*)sm.Bhi + off));
                    ldsm_x4t(bl[ntp], smem_u32((char*)sm.Blo + off));
                }
                #pragma unroll
                for (int nt = 0; nt < 4; nt++) {
                    const uint32_t* b2h = &bh[nt >> 1][(nt & 1) * 2];
                    const uint32_t* b2l = &bl[nt >> 1][(nt & 1) * 2];
                    #pragma unroll
                    for (int rt = 0; rt < 2; rt++) {
                        mma_f16_k16(C[rt][nt], Af[rt][ks], b2h);
                        mma_f16_k16(C[rt][nt], Af[rt][ks], b2l);
                    }
                }
            }
            #pragma unroll
            for (int nt = 0; nt < 4; nt++) {
                float2 ww = *(const float2*)&sm.w3s[(nh * 4 + nt) * 8 + c2i];
                #pragma unroll
                for (int rt = 0; rt < 2; rt++) {
                    float t0 = tanh_approx(C[rt][nt][0]);
                    float t1 = tanh_approx(C[rt][nt][1]);
                    float t2 = tanh_approx(C[rt][nt][2]);
                    float t3 = tanh_approx(C[rt][nt][3]);
                    ee[rt * 2 + 0] = fmaf(t0, ww.x, fmaf(t1, ww.y, ee[rt * 2 + 0]));
                    ee[rt * 2 + 1] = fmaf(t2, ww.x, fmaf(t3, ww.y, ee[rt * 2 + 1]));
                }
            }
        }

        // ---- reduce + store ----
        #pragma unroll
        for (int i = 0; i < 4; i++) {
            ee[i] += __shfl_xor_sync(0xFFFFFFFFu, ee[i], 1);
            ee[i] += __shfl_xor_sync(0xFFFFFFFFu, ee[i], 2);
        }
        if ((lane & 3) == 0) {
            float e3 = sm.b3s;
            int q = lane >> 2;
            int r = sBase + t * M_TILE + wid * 32 + q;
            out[(size_t)(r)      * A_TOT + a] = ee[0] + e3;
            out[(size_t)(r + 8)  * A_TOT + a] = ee[1] + e3;
            out[(size_t)(r + 16) * A_TOT + a] = ee[2] + e3;
            out[(size_t)(r + 24) * A_TOT + a] = ee[3] + e3;
        }

        // ---- commit prefetched g, single barrier per tile ----
        if (t + 1 < TILES) {
            #pragma unroll
            for (int p = 0; p < 5; p++) {
                int e = p * NTHR + tid;
                int row = e / 5, d = e - row * 5;
                sm.G[1 - buf][row][d] = gn[p];
            }
            __syncthreads();
        }
    }
}

extern "C" void kernel_launch(void* const* d_in, const int* in_sizes, int n_in,
                              void* d_out, int out_size)
{
    const float* g  = (const float*)d_in[0];
    const float* W1 = (const float*)d_in[1];
    const float* b1 = (const float*)d_in[2];
    const float* W2 = (const float*)d_in[3];
    const float* b2 = (const float*)d_in[4];
    const float* W3 = (const float*)d_in[5];
    const float* b3 = (const float*)d_in[6];
    float* out = (float*)d_out;

    mlp_kernel<<<dim3(S_TOT / SPT, A_TOT), NTHR>>>(g, W1, b1, W2, b2, W3, b3, out);
}